// round 11
// baseline (speedup 1.0000x reference)
#include <cuda_runtime.h>

#define N       8192
#define IN_DIM  512
#define OUT     64
#define R_ROWS  32
#define TJ      128
#define NTILES  (N / TJ)
#define GR      64          // rows per block in the GEMM prologue
#define HS_LD   68          // h_s row stride (272B: 16B-aligned + bank skew)
#define WBUF    (R_ROWS * TJ)     // 4096 floats per w buffer
#define HBUF    (TJ * HS_LD)      // 8704 floats per h buffer

// Scratch (device globals — no allocation allowed)
__device__ float g_h[N * OUT];
__device__ float g_h1[N];
__device__ float g_h2[N];
__device__ float g_P[N];    // exp(h1)
__device__ float g_R[N];    // exp(0.2*h1)
__device__ float g_Q[N];    // exp(h2)
__device__ float g_S[N];    // exp(0.2*h2)

// ---------------------------------------------------------------------------
// Packed f32x2 helpers (Blackwell FFMA2 — only reachable via PTX)
// ---------------------------------------------------------------------------
__device__ __forceinline__ unsigned long long pack2(float x) {
    unsigned long long r;
    asm("mov.b64 %0, {%1, %1};" : "=l"(r) : "r"(__float_as_uint(x)));
    return r;
}
__device__ __forceinline__ void fma2(unsigned long long& d,
                                     unsigned long long a,
                                     unsigned long long b) {
    asm("fma.rn.f32x2 %0, %1, %2, %0;" : "+l"(d) : "l"(a), "l"(b));
}
__device__ __forceinline__ unsigned long long add2(unsigned long long a,
                                                   unsigned long long b) {
    unsigned long long r;
    asm("add.rn.f32x2 %0, %1, %2;" : "=l"(r) : "l"(a), "l"(b));
    return r;
}
__device__ __forceinline__ float lo2(unsigned long long v) {
    unsigned int a, b;
    asm("mov.b64 {%0, %1}, %2;" : "=r"(a), "=r"(b) : "l"(v));
    return __uint_as_float(a);
}
__device__ __forceinline__ float hi2(unsigned long long v) {
    unsigned int a, b;
    asm("mov.b64 {%0, %1}, %2;" : "=r"(a), "=r"(b) : "l"(v));
    return __uint_as_float(b);
}

// ---------------------------------------------------------------------------
// Kernel 1: blocked GEMM  h = features @ W  + h1/h2 + exp factor tables
//   exp(lrelu(h1_i+h2_j)) = (x>0) ? P_i·Q_j : R_i·S_j ; softmax shift dropped
//   (row normalization cancels constants; overflow needs h1+h2>88 ~ 16σ).
// ---------------------------------------------------------------------------
__global__ __launch_bounds__(256) void gemm_h_kernel(
    const float* __restrict__ features,
    const float* __restrict__ W,
    const float* __restrict__ a)
{
    __shared__ float fs[GR][68];
    __shared__ float Ws[64][68];
    __shared__ float as[2 * OUT];

    const int t    = threadIdx.x;
    const int row0 = blockIdx.x * GR;
    const int ro   = t >> 4;          // 0..15 -> rows ro*4 .. ro*4+3
    const int co   = t & 15;          // 0..15 -> outs co*4 .. co*4+3

    if (t < 2 * OUT) as[t] = a[t];

    unsigned long long acc[4][2];     // 4 rows x 4 outs (2 f32x2)
    #pragma unroll
    for (int r = 0; r < 4; r++) { acc[r][0] = 0ull; acc[r][1] = 0ull; }

    for (int kc = 0; kc < IN_DIM / 64; kc++) {
        __syncthreads();
        #pragma unroll
        for (int i = 0; i < 4; i++) {
            int idx = t + 256 * i;            // 0..1023 float4 slots
            int rr  = idx >> 4;
            int c4  = idx & 15;
            float4 fv = *(const float4*)(features +
                         (long long)(row0 + rr) * IN_DIM + kc * 64 + c4 * 4);
            *(float4*)&fs[rr][c4 * 4] = fv;
            float4 wv = *(const float4*)(W +
                         (long long)(kc * 64 + rr) * OUT + c4 * 4);
            *(float4*)&Ws[rr][c4 * 4] = wv;
        }
        __syncthreads();

        #pragma unroll 4
        for (int k = 0; k < 64; k++) {
            unsigned long long w0 = *(const unsigned long long*)&Ws[k][co * 4];
            unsigned long long w1 = *(const unsigned long long*)&Ws[k][co * 4 + 2];
            #pragma unroll
            for (int r = 0; r < 4; r++) {
                unsigned long long fv = pack2(fs[ro * 4 + r][k]);
                fma2(acc[r][0], fv, w0);
                fma2(acc[r][1], fv, w1);
            }
        }
    }

    #pragma unroll
    for (int r = 0; r < 4; r++) {
        int row = row0 + ro * 4 + r;
        float4 hv = make_float4(lo2(acc[r][0]), hi2(acc[r][0]),
                                lo2(acc[r][1]), hi2(acc[r][1]));
        *(float4*)(g_h + (long long)row * OUT + co * 4) = hv;
        float p1 = hv.x * as[co * 4] + hv.y * as[co * 4 + 1] +
                   hv.z * as[co * 4 + 2] + hv.w * as[co * 4 + 3];
        float p2 = hv.x * as[OUT + co * 4]     + hv.y * as[OUT + co * 4 + 1] +
                   hv.z * as[OUT + co * 4 + 2] + hv.w * as[OUT + co * 4 + 3];
        #pragma unroll
        for (int o = 8; o > 0; o >>= 1) {
            p1 += __shfl_down_sync(0xffffffffu, p1, o, 16);
            p2 += __shfl_down_sync(0xffffffffu, p2, o, 16);
        }
        if (co == 0) {
            g_h1[row] = p1;
            g_h2[row] = p2;
            g_P[row]  = __expf(p1);
            g_R[row]  = __expf(0.2f * p1);
            g_Q[row]  = __expf(p2);
            g_S[row]  = __expf(0.2f * p2);
        }
    }
}

// ---------------------------------------------------------------------------
// Kernel 2: fused masked-softmax attention + AV + ELU, double-buffered:
//   iter t: build w(t+1)->buf^1, stage h(t+1)->buf^1, prefetch adj(t+2),
//           PhaseB(t) from buf, ONE barrier.
// R10 failure root-cause: missing barrier between rowsum zeroing (warp 0)
// and the prologue's cross-warp rowsum accumulation — restored below.
// ---------------------------------------------------------------------------
__device__ __forceinline__ float build_w(
    const int4* av4, const float4* __restrict__ h2p,
    const float4* __restrict__ Qp, const float4* __restrict__ Sp,
    float* __restrict__ wrow, float h1, float Pi, float Ri, int sub)
{
    float lsum = 0.f;
    #pragma unroll
    for (int k = 0; k < 4; k++) {
        int idx = sub + 8 * k;              // float4 index within the tile row
        int4   av  = av4[k];
        float4 h2v = h2p[idx];
        float4 Qv  = Qp[idx];
        float4 Sv  = Sp[idx];
        float4 wv;
        float x;
        x = h1 + h2v.x;
        wv.x = (av.x > 0) ? ((x > 0.f ? Pi : Ri) * (x > 0.f ? Qv.x : Sv.x)) : 0.f;
        x = h1 + h2v.y;
        wv.y = (av.y > 0) ? ((x > 0.f ? Pi : Ri) * (x > 0.f ? Qv.y : Sv.y)) : 0.f;
        x = h1 + h2v.z;
        wv.z = (av.z > 0) ? ((x > 0.f ? Pi : Ri) * (x > 0.f ? Qv.z : Sv.z)) : 0.f;
        x = h1 + h2v.w;
        wv.w = (av.w > 0) ? ((x > 0.f ? Pi : Ri) * (x > 0.f ? Qv.w : Sv.w)) : 0.f;
        ((float4*)wrow)[idx] = wv;
        lsum += (wv.x + wv.y) + (wv.z + wv.w);
    }
    return lsum;
}

// Coalesced stage of h tile [j0..j0+TJ) into an h buffer (row stride HS_LD).
__device__ __forceinline__ void stage_h(float* __restrict__ hbuf, int j0, int t)
{
    #pragma unroll
    for (int s = 0; s < 8; s++) {
        int idx = t + 256 * s;              // 0..2047 float4 slots
        int row = idx >> 4;
        int c4  = idx & 15;
        float4 v = *(const float4*)(g_h + (long long)(j0 + row) * OUT + c4 * 4);
        *(float4*)&hbuf[row * HS_LD + c4 * 4] = v;
    }
}

__global__ __launch_bounds__(256, 2) void gat_main_kernel(
    const int* __restrict__ adj,
    float* __restrict__ out)
{
    extern __shared__ float smem[];
    // layout: w0 | w1 | h0 | h1 | rowsum
    float* w_b[2] = { smem, smem + WBUF };
    float* h_b[2] = { smem + 2 * WBUF, smem + 2 * WBUF + HBUF };
    float* rowsum = smem + 2 * WBUF + 2 * HBUF;

    const int t    = threadIdx.x;
    const int row0 = blockIdx.x * R_ROWS;

    if (t < R_ROWS) rowsum[t] = 0.f;

    // Phase-B mapping: 4 row-groups(8) x 8 dim-groups(8) x 8 j-chunks
    const int rg  = t >> 6;
    const int dgp = (t >> 3) & 7;
    const int jc  = t & 7;

    // Phase-A mapping: row = t>>3, 8 threads per row
    const int ra  = t >> 3;
    const int sub = t & 7;
    const float h1 = g_h1[row0 + ra];
    const float Pi = g_P[row0 + ra];
    const float Ri = g_R[row0 + ra];
    const int4* adjrow = (const int4*)(adj + (long long)(row0 + ra) * N);

    unsigned long long acc[8][4];
    #pragma unroll
    for (int r = 0; r < 8; r++)
        #pragma unroll
        for (int p = 0; p < 4; p++) acc[r][p] = 0ull;

    __syncthreads();   // rowsum zeroed (warp 0) before ANY cross-warp += below

    // ---- prologue: build tile 0 into buf 0, prefetch adj(1) ----
    int4 av4[4];
    {
        #pragma unroll
        for (int k = 0; k < 4; k++) av4[k] = __ldcs(&adjrow[sub + 8 * k]);
        float lsum = build_w(av4, (const float4*)g_h2, (const float4*)g_Q,
                             (const float4*)g_S, w_b[0] + ra * TJ,
                             h1, Pi, Ri, sub);
        #pragma unroll
        for (int o = 4; o > 0; o >>= 1)
            lsum += __shfl_down_sync(0xffffffffu, lsum, o, 8);
        if (sub == 0) rowsum[ra] += lsum;
        stage_h(h_b[0], 0, t);
        // prefetch adj(1)
        const int4* ap = adjrow + (TJ / 4);
        #pragma unroll
        for (int k = 0; k < 4; k++) av4[k] = __ldcs(&ap[sub + 8 * k]);
    }
    __syncthreads();

    for (int tile = 0; tile < NTILES; tile++) {
        const int buf = tile & 1;

        // ---- build w(tile+1)+stage h(tile+1) into buf^1 (overlaps PhaseB) --
        if (tile + 1 < NTILES) {
            const int jn = (tile + 1) * TJ;
            float lsum = build_w(av4, (const float4*)(g_h2 + jn),
                                 (const float4*)(g_Q + jn),
                                 (const float4*)(g_S + jn),
                                 w_b[buf ^ 1] + ra * TJ, h1, Pi, Ri, sub);
            #pragma unroll
            for (int o = 4; o > 0; o >>= 1)
                lsum += __shfl_down_sync(0xffffffffu, lsum, o, 8);
            if (sub == 0) rowsum[ra] += lsum;
            stage_h(h_b[buf ^ 1], jn, t);
            if (tile + 2 < NTILES) {
                const int4* ap = adjrow + (tile + 2) * (TJ / 4);
                #pragma unroll
                for (int k = 0; k < 4; k++) av4[k] = __ldcs(&ap[sub + 8 * k]);
            }
        }

        // ---------------- Phase B: acc += w * h (all smem) ----------------
        const float* ws = w_b[buf];
        const float* hs = h_b[buf];
        #pragma unroll 2
        for (int i = 0; i < TJ / 8; i++) {
            const int j = jc + 8 * i;       // stride-8 walk: conflict-free LDS
            const ulonglong2* hp =
                (const ulonglong2*)(hs + j * HS_LD + dgp * 8);
            ulonglong2 hA = hp[0];          // dims dgp*8 + 0..3
            ulonglong2 hB = hp[1];          // dims dgp*8 + 4..7
            #pragma unroll
            for (int r = 0; r < 8; r++) {
                unsigned long long wp = pack2(ws[(rg * 8 + r) * TJ + j]);
                fma2(acc[r][0], wp, hA.x);
                fma2(acc[r][1], wp, hA.y);
                fma2(acc[r][2], wp, hB.x);
                fma2(acc[r][3], wp, hB.y);
            }
        }

        __syncthreads();     // one barrier per tile: next buf built + this read
    }

    // -------- Epilogue: shuffle-reduce the 8 jc-chunks (same warp, width 8) --
    #pragma unroll
    for (int r = 0; r < 8; r++)
        #pragma unroll
        for (int p = 0; p < 4; p++) {
            #pragma unroll
            for (int o = 4; o > 0; o >>= 1)
                acc[r][p] = add2(acc[r][p],
                                 __shfl_down_sync(0xffffffffu, acc[r][p], o, 8));
        }

    if (jc == 0) {
        #pragma unroll
        for (int r = 0; r < 8; r++) {
            int row   = row0 + rg * 8 + r;
            float inv = 1.0f / rowsum[rg * 8 + r];
            float f0 = lo2(acc[r][0]) * inv, f1 = hi2(acc[r][0]) * inv;
            float f2 = lo2(acc[r][1]) * inv, f3 = hi2(acc[r][1]) * inv;
            float f4 = lo2(acc[r][2]) * inv, f5 = hi2(acc[r][2]) * inv;
            float f6 = lo2(acc[r][3]) * inv, f7 = hi2(acc[r][3]) * inv;
            f0 = (f0 > 0.f) ? f0 : expm1f(f0);
            f1 = (f1 > 0.f) ? f1 : expm1f(f1);
            f2 = (f2 > 0.f) ? f2 : expm1f(f2);
            f3 = (f3 > 0.f) ? f3 : expm1f(f3);
            f4 = (f4 > 0.f) ? f4 : expm1f(f4);
            f5 = (f5 > 0.f) ? f5 : expm1f(f5);
            f6 = (f6 > 0.f) ? f6 : expm1f(f6);
            f7 = (f7 > 0.f) ? f7 : expm1f(f7);
            float* op = out + (long long)row * OUT + dgp * 8;
            *(float4*)(op)     = make_float4(f0, f1, f2, f3);
            *(float4*)(op + 4) = make_float4(f4, f5, f6, f7);
        }
    }
}

// ---------------------------------------------------------------------------
extern "C" void kernel_launch(void* const* d_in, const int* in_sizes, int n_in,
                              void* d_out, int out_size)
{
    const float* features = (const float*)d_in[0];
    const int*   adj      = (const int*)d_in[1];
    const float* W        = (const float*)d_in[2];
    const float* a        = (const float*)d_in[3];
    float*       out      = (float*)d_out;

    (void)in_sizes; (void)n_in; (void)out_size;

    const int smem_bytes =
        (2 * WBUF + 2 * HBUF + R_ROWS) * (int)sizeof(float);   // ~100.1 KB
    cudaFuncSetAttribute(gat_main_kernel,
                         cudaFuncAttributeMaxDynamicSharedMemorySize, smem_bytes);

    gemm_h_kernel<<<N / GR, 256>>>(features, W, a);
    gat_main_kernel<<<N / R_ROWS, 256, smem_bytes>>>(adj, out);
}

// round 16
// speedup vs baseline: 1.4001x; 1.4001x over previous
#include <cuda_runtime.h>

#define N       8192
#define IN_DIM  512
#define OUT     64
#define R_ROWS  32
#define TJ      128
#define NTILES  (N / TJ)
#define GR      64          // rows per block in the GEMM prologue
#define HS_LD   68          // h_s row stride (272B: 16B-aligned + bank skew)
#define WBUF    (R_ROWS * TJ)     // 4096 floats per w buffer
#define HBUF    (TJ * HS_LD)      // 8704 floats per h buffer

// Scratch (device globals — no allocation allowed)
__device__ float g_h[N * OUT];
__device__ float g_h1[N];
__device__ float g_h2[N];
__device__ float g_P[N];    // exp(h1)
__device__ float g_R[N];    // exp(0.2*h1)
__device__ float g_Q[N];    // exp(h2)
__device__ float g_S[N];    // exp(0.2*h2)

// ---------------------------------------------------------------------------
// Packed f32x2 helpers (Blackwell FFMA2 — only reachable via PTX)
// ---------------------------------------------------------------------------
__device__ __forceinline__ unsigned long long pack2(float x) {
    unsigned long long r;
    asm("mov.b64 %0, {%1, %1};" : "=l"(r) : "r"(__float_as_uint(x)));
    return r;
}
__device__ __forceinline__ void fma2(unsigned long long& d,
                                     unsigned long long a,
                                     unsigned long long b) {
    asm("fma.rn.f32x2 %0, %1, %2, %0;" : "+l"(d) : "l"(a), "l"(b));
}
__device__ __forceinline__ unsigned long long add2(unsigned long long a,
                                                   unsigned long long b) {
    unsigned long long r;
    asm("add.rn.f32x2 %0, %1, %2;" : "=l"(r) : "l"(a), "l"(b));
    return r;
}
__device__ __forceinline__ float lo2(unsigned long long v) {
    unsigned int a, b;
    asm("mov.b64 {%0, %1}, %2;" : "=r"(a), "=r"(b) : "l"(v));
    return __uint_as_float(a);
}
__device__ __forceinline__ float hi2(unsigned long long v) {
    unsigned int a, b;
    asm("mov.b64 {%0, %1}, %2;" : "=r"(a), "=r"(b) : "l"(v));
    return __uint_as_float(b);
}

// cp.async 16B GMEM->SMEM (no register dependency; overlaps Phase B)
__device__ __forceinline__ void cp16(unsigned int dst_smem, const void* src) {
    asm volatile("cp.async.cg.shared.global [%0], [%1], 16;\n"
                 :: "r"(dst_smem), "l"(src));
}
__device__ __forceinline__ void cp_commit() {
    asm volatile("cp.async.commit_group;\n");
}
__device__ __forceinline__ void cp_wait0() {
    asm volatile("cp.async.wait_group 0;\n" ::: "memory");
}

// ---------------------------------------------------------------------------
// Kernel 1: blocked GEMM  h = features @ W  + h1/h2 + exp factor tables
//   exp(lrelu(h1_i+h2_j)) = (x>0) ? P_i·Q_j : R_i·S_j ; softmax shift dropped
//   (row normalization cancels constants; overflow needs h1+h2>88 ~ 16σ).
// ---------------------------------------------------------------------------
__global__ __launch_bounds__(256) void gemm_h_kernel(
    const float* __restrict__ features,
    const float* __restrict__ W,
    const float* __restrict__ a)
{
    __shared__ float fs[GR][68];
    __shared__ float Ws[64][68];
    __shared__ float as[2 * OUT];

    const int t    = threadIdx.x;
    const int row0 = blockIdx.x * GR;
    const int ro   = t >> 4;          // 0..15 -> rows ro*4 .. ro*4+3
    const int co   = t & 15;          // 0..15 -> outs co*4 .. co*4+3

    if (t < 2 * OUT) as[t] = a[t];

    unsigned long long acc[4][2];     // 4 rows x 4 outs (2 f32x2)
    #pragma unroll
    for (int r = 0; r < 4; r++) { acc[r][0] = 0ull; acc[r][1] = 0ull; }

    for (int kc = 0; kc < IN_DIM / 64; kc++) {
        __syncthreads();
        #pragma unroll
        for (int i = 0; i < 4; i++) {
            int idx = t + 256 * i;            // 0..1023 float4 slots
            int rr  = idx >> 4;
            int c4  = idx & 15;
            float4 fv = *(const float4*)(features +
                         (long long)(row0 + rr) * IN_DIM + kc * 64 + c4 * 4);
            *(float4*)&fs[rr][c4 * 4] = fv;
            float4 wv = *(const float4*)(W +
                         (long long)(kc * 64 + rr) * OUT + c4 * 4);
            *(float4*)&Ws[rr][c4 * 4] = wv;
        }
        __syncthreads();

        #pragma unroll 4
        for (int k = 0; k < 64; k++) {
            unsigned long long w0 = *(const unsigned long long*)&Ws[k][co * 4];
            unsigned long long w1 = *(const unsigned long long*)&Ws[k][co * 4 + 2];
            #pragma unroll
            for (int r = 0; r < 4; r++) {
                unsigned long long fv = pack2(fs[ro * 4 + r][k]);
                fma2(acc[r][0], fv, w0);
                fma2(acc[r][1], fv, w1);
            }
        }
    }

    #pragma unroll
    for (int r = 0; r < 4; r++) {
        int row = row0 + ro * 4 + r;
        float4 hv = make_float4(lo2(acc[r][0]), hi2(acc[r][0]),
                                lo2(acc[r][1]), hi2(acc[r][1]));
        *(float4*)(g_h + (long long)row * OUT + co * 4) = hv;
        float p1 = hv.x * as[co * 4] + hv.y * as[co * 4 + 1] +
                   hv.z * as[co * 4 + 2] + hv.w * as[co * 4 + 3];
        float p2 = hv.x * as[OUT + co * 4]     + hv.y * as[OUT + co * 4 + 1] +
                   hv.z * as[OUT + co * 4 + 2] + hv.w * as[OUT + co * 4 + 3];
        #pragma unroll
        for (int o = 8; o > 0; o >>= 1) {
            p1 += __shfl_down_sync(0xffffffffu, p1, o, 16);
            p2 += __shfl_down_sync(0xffffffffu, p2, o, 16);
        }
        if (co == 0) {
            g_h1[row] = p1;
            g_h2[row] = p2;
            g_P[row]  = __expf(p1);
            g_R[row]  = __expf(0.2f * p1);
            g_Q[row]  = __expf(p2);
            g_S[row]  = __expf(0.2f * p2);
        }
    }
}

// ---------------------------------------------------------------------------
// Kernel 2: fused masked-softmax attention + AV + ELU, double-buffered with
// cp.async h staging (R11 post-mortem: register-path staging serialized the
// pipeline; cp.async has no reg dependency so the copy hides under PhaseB).
//   iter t: cp.async h(t+1)->hbuf^1 ; PhaseB(t) ; build w(t+1)->wbuf^1 ;
//           prefetch adj(t+2) ; cp.async.wait ; ONE barrier.
// ---------------------------------------------------------------------------
__device__ __forceinline__ float build_w(
    const int4* av4, const float4* __restrict__ h2p,
    const float4* __restrict__ Qp, const float4* __restrict__ Sp,
    float* __restrict__ wrow, float h1, float Pi, float Ri, int sub)
{
    float lsum = 0.f;
    #pragma unroll
    for (int k = 0; k < 4; k++) {
        int idx = sub + 8 * k;              // float4 index within the tile row
        int4   av  = av4[k];
        float4 h2v = h2p[idx];
        float4 Qv  = Qp[idx];
        float4 Sv  = Sp[idx];
        float4 wv;
        float x;
        x = h1 + h2v.x;
        wv.x = (av.x > 0) ? ((x > 0.f ? Pi : Ri) * (x > 0.f ? Qv.x : Sv.x)) : 0.f;
        x = h1 + h2v.y;
        wv.y = (av.y > 0) ? ((x > 0.f ? Pi : Ri) * (x > 0.f ? Qv.y : Sv.y)) : 0.f;
        x = h1 + h2v.z;
        wv.z = (av.z > 0) ? ((x > 0.f ? Pi : Ri) * (x > 0.f ? Qv.z : Sv.z)) : 0.f;
        x = h1 + h2v.w;
        wv.w = (av.w > 0) ? ((x > 0.f ? Pi : Ri) * (x > 0.f ? Qv.w : Sv.w)) : 0.f;
        ((float4*)wrow)[idx] = wv;
        lsum += (wv.x + wv.y) + (wv.z + wv.w);
    }
    return lsum;
}

// Async stage of h tile [j0..j0+TJ) into an h buffer (row stride HS_LD).
__device__ __forceinline__ void stage_h_async(unsigned int hbuf_addr, int j0, int t)
{
    #pragma unroll
    for (int s = 0; s < 8; s++) {
        int idx = t + 256 * s;              // 0..2047 float4 slots
        int row = idx >> 4;
        int c4  = idx & 15;
        cp16(hbuf_addr + (unsigned)(row * HS_LD + c4 * 4) * 4u,
             g_h + (long long)(j0 + row) * OUT + c4 * 4);
    }
}

__global__ __launch_bounds__(256, 2) void gat_main_kernel(
    const int* __restrict__ adj,
    float* __restrict__ out)
{
    extern __shared__ float smem[];
    // layout: w0 | w1 | h0 | h1 | rowsum
    float* w0 = smem;
    float* w1 = smem + WBUF;
    float* h0 = smem + 2 * WBUF;
    float* h1b = smem + 2 * WBUF + HBUF;
    float* rowsum = smem + 2 * WBUF + 2 * HBUF;
    const unsigned int smem_sa = (unsigned int)__cvta_generic_to_shared(smem);
    const unsigned int h_sa[2] = { smem_sa + 2u * WBUF * 4u,
                                   smem_sa + (2u * WBUF + HBUF) * 4u };

    const int t    = threadIdx.x;
    const int row0 = blockIdx.x * R_ROWS;

    if (t < R_ROWS) rowsum[t] = 0.f;

    // Phase-B mapping: 4 row-groups(8) x 8 dim-groups(8) x 8 j-chunks
    const int rg  = t >> 6;
    const int dgp = (t >> 3) & 7;
    const int jc  = t & 7;

    // Phase-A mapping: row = t>>3, 8 threads per row
    const int ra  = t >> 3;
    const int sub = t & 7;
    const float h1 = g_h1[row0 + ra];
    const float Pi = g_P[row0 + ra];
    const float Ri = g_R[row0 + ra];
    const int4* adjrow = (const int4*)(adj + (long long)(row0 + ra) * N);

    unsigned long long acc[8][4];
    #pragma unroll
    for (int r = 0; r < 8; r++)
        #pragma unroll
        for (int p = 0; p < 4; p++) acc[r][p] = 0ull;

    __syncthreads();   // rowsum zeroed (warp 0) before ANY cross-warp += below

    // ---- prologue: async-stage h(0), build w(0), prefetch adj(1) ----
    int4 av4[4];
    {
        stage_h_async(h_sa[0], 0, t);
        cp_commit();
        #pragma unroll
        for (int k = 0; k < 4; k++) av4[k] = __ldcs(&adjrow[sub + 8 * k]);
        float lsum = build_w(av4, (const float4*)g_h2, (const float4*)g_Q,
                             (const float4*)g_S, w0 + ra * TJ,
                             h1, Pi, Ri, sub);
        #pragma unroll
        for (int o = 4; o > 0; o >>= 1)
            lsum += __shfl_down_sync(0xffffffffu, lsum, o, 8);
        if (sub == 0) rowsum[ra] += lsum;
        // prefetch adj(1)
        const int4* ap = adjrow + (TJ / 4);
        #pragma unroll
        for (int k = 0; k < 4; k++) av4[k] = __ldcs(&ap[sub + 8 * k]);
        cp_wait0();
    }
    __syncthreads();

    for (int tile = 0; tile < NTILES; tile++) {
        const int buf = tile & 1;

        // ---- async-stage h(tile+1) into buf^1: hides under PhaseB ----
        if (tile + 1 < NTILES) {
            stage_h_async(h_sa[buf ^ 1], (tile + 1) * TJ, t);
            cp_commit();
        }

        // ---------------- Phase B: acc += w * h (all smem) ----------------
        const float* ws = buf ? w1 : w0;
        const float* hs = buf ? h1b : h0;
        #pragma unroll 2
        for (int i = 0; i < TJ / 8; i++) {
            const int j = jc + 8 * i;       // stride-8 walk: conflict-free LDS
            const ulonglong2* hp =
                (const ulonglong2*)(hs + j * HS_LD + dgp * 8);
            ulonglong2 hA = hp[0];          // dims dgp*8 + 0..3
            ulonglong2 hB = hp[1];          // dims dgp*8 + 4..7
            #pragma unroll
            for (int r = 0; r < 8; r++) {
                unsigned long long wp = pack2(ws[(rg * 8 + r) * TJ + j]);
                fma2(acc[r][0], wp, hA.x);
                fma2(acc[r][1], wp, hA.y);
                fma2(acc[r][2], wp, hB.x);
                fma2(acc[r][3], wp, hB.y);
            }
        }

        // ---- build w(tile+1) into buf^1 (short, L1-hit) ----
        if (tile + 1 < NTILES) {
            const int jn = (tile + 1) * TJ;
            float* wd = (buf ? w0 : w1);
            float lsum = build_w(av4, (const float4*)(g_h2 + jn),
                                 (const float4*)(g_Q + jn),
                                 (const float4*)(g_S + jn),
                                 wd + ra * TJ, h1, Pi, Ri, sub);
            #pragma unroll
            for (int o = 4; o > 0; o >>= 1)
                lsum += __shfl_down_sync(0xffffffffu, lsum, o, 8);
            if (sub == 0) rowsum[ra] += lsum;
            if (tile + 2 < NTILES) {
                const int4* ap = adjrow + (tile + 2) * (TJ / 4);
                #pragma unroll
                for (int k = 0; k < 4; k++) av4[k] = __ldcs(&ap[sub + 8 * k]);
            }
        }

        cp_wait0();          // h(tile+1) resident
        __syncthreads();     // one barrier per tile
    }

    // -------- Epilogue: shuffle-reduce the 8 jc-chunks (same warp, width 8) --
    #pragma unroll
    for (int r = 0; r < 8; r++)
        #pragma unroll
        for (int p = 0; p < 4; p++) {
            #pragma unroll
            for (int o = 4; o > 0; o >>= 1)
                acc[r][p] = add2(acc[r][p],
                                 __shfl_down_sync(0xffffffffu, acc[r][p], o, 8));
        }

    if (jc == 0) {
        #pragma unroll
        for (int r = 0; r < 8; r++) {
            int row   = row0 + rg * 8 + r;
            float inv = 1.0f / rowsum[rg * 8 + r];
            float f0 = lo2(acc[r][0]) * inv, f1 = hi2(acc[r][0]) * inv;
            float f2 = lo2(acc[r][1]) * inv, f3 = hi2(acc[r][1]) * inv;
            float f4 = lo2(acc[r][2]) * inv, f5 = hi2(acc[r][2]) * inv;
            float f6 = lo2(acc[r][3]) * inv, f7 = hi2(acc[r][3]) * inv;
            f0 = (f0 > 0.f) ? f0 : expm1f(f0);
            f1 = (f1 > 0.f) ? f1 : expm1f(f1);
            f2 = (f2 > 0.f) ? f2 : expm1f(f2);
            f3 = (f3 > 0.f) ? f3 : expm1f(f3);
            f4 = (f4 > 0.f) ? f4 : expm1f(f4);
            f5 = (f5 > 0.f) ? f5 : expm1f(f5);
            f6 = (f6 > 0.f) ? f6 : expm1f(f6);
            f7 = (f7 > 0.f) ? f7 : expm1f(f7);
            float* op = out + (long long)row * OUT + dgp * 8;
            *(float4*)(op)     = make_float4(f0, f1, f2, f3);
            *(float4*)(op + 4) = make_float4(f4, f5, f6, f7);
        }
    }
}

// ---------------------------------------------------------------------------
extern "C" void kernel_launch(void* const* d_in, const int* in_sizes, int n_in,
                              void* d_out, int out_size)
{
    const float* features = (const float*)d_in[0];
    const int*   adj      = (const int*)d_in[1];
    const float* W        = (const float*)d_in[2];
    const float* a        = (const float*)d_in[3];
    float*       out      = (float*)d_out;

    (void)in_sizes; (void)n_in; (void)out_size;

    const int smem_bytes =
        (2 * WBUF + 2 * HBUF + R_ROWS) * (int)sizeof(float);   // ~100.1 KB
    cudaFuncSetAttribute(gat_main_kernel,
                         cudaFuncAttributeMaxDynamicSharedMemorySize, smem_bytes);

    gemm_h_kernel<<<N / GR, 256>>>(features, W, a);
    gat_main_kernel<<<N / R_ROWS, 256, smem_bytes>>>(adj, out);
}